// round 15
// baseline (speedup 1.0000x reference)
#include <cuda_runtime.h>
#include <cuda_fp16.h>
#include <cstdint>
#include <cstddef>

// ===========================================================================
// Flash attention via mma.sync.m16n8k16 (fp16-split for fp32 accuracy).
// Q,K,V fp32 [D=128, N=8192] feature-major. out[d,q] fp32.
// R15: R14 core + fused kv-split combine (last-arriving CTA per q-block merges
//      partials in-kernel; atomic counter + threadfence) + noop launches gone.
// grid = (64 q-blocks, 2 kv-splits). Two launches total: cvt, attn.
// ===========================================================================

namespace {

constexpr int D_ = 128;
constexpr int N_ = 8192;
constexpr int BQ = 128;
constexpr int BK = 64;
constexpr int SPLIT = 2;
constexpr int KVLEN = N_ / SPLIT;   // 4096
constexpr int NT = KVLEN / BK;      // 64 tiles
constexpr int NTHREADS = 256;

constexpr int QSTR = 136;           // halves per Q row (272 B, conflict-free)
constexpr int TSTR = 72;            // halves per K/V tile row (144 B)

// smem byte offsets
constexpr int SMBAR = 0;            // 7 mbarriers x 8 B + 4 B scratch
constexpr int SQLO  = 128;
constexpr int SBUF  = SQLO + D_ * QSTR * 2;         // 128+34816 = 34944
constexpr int SUB   = D_ * TSTR * 2;                // 18432 per sub-tile
constexpr int KH_OFF = 0, KL_OFF = SUB, VH_OFF = 2 * SUB;
constexpr int BUFB = 3 * SUB;                       // 55296
constexpr int NBUF = 3;
constexpr int SMEM_BYTES = SBUF + NBUF * BUFB;      // 200,832

constexpr float LOG2E  = 1.4426950408889634f;
constexpr float THRESH = 11.5f;                     // ~8 nats, in log2 units

// pre-split K (hi/lo) and V (single fp16), written once by cvt_kernel
__device__ __half g_Khi[D_][N_];
__device__ __half g_Klo[D_][N_];
__device__ __half g_Vhi[D_][N_];

// kv-split combine scratch (m in log2 units)
__device__ float g_Op[SPLIT][D_][N_];
__device__ float g_m[SPLIT][N_];
__device__ float g_l[SPLIT][N_];
__device__ unsigned int g_sync[N_ / BQ];   // per-qb arrival counters (zeroed; reset each use)

__device__ __forceinline__ uint32_t smem_u32(const void* p) {
    uint32_t a;
    asm("{ .reg .u64 t; cvta.to.shared.u64 t, %1; cvt.u32.u64 %0, t; }" : "=r"(a) : "l"(p));
    return a;
}
__device__ __forceinline__ void cp16(uint32_t s, const void* g) {
    asm volatile("cp.async.cg.shared.global [%0], [%1], 16;\n" :: "r"(s), "l"(g));
}
__device__ __forceinline__ void mbar_init(uint32_t mb, uint32_t cnt) {
    asm volatile("mbarrier.init.shared.b64 [%0], %1;" :: "r"(mb), "r"(cnt) : "memory");
}
__device__ __forceinline__ void mbar_arrive(uint32_t mb) {
    uint64_t s;
    asm volatile("mbarrier.arrive.shared.b64 %0, [%1];" : "=l"(s) : "r"(mb) : "memory");
}
__device__ __forceinline__ void cpasync_mbar_arrive(uint32_t mb) {
    asm volatile("cp.async.mbarrier.arrive.noinc.shared.b64 [%0];" :: "r"(mb) : "memory");
}
__device__ __forceinline__ void mbar_wait(uint32_t mb, uint32_t par) {
    uint32_t done = 0;
    while (!done) {
        asm volatile("{\n\t.reg .pred p;\n\t"
                     "mbarrier.test_wait.parity.shared.b64 p, [%1], %2;\n\t"
                     "selp.b32 %0, 1, 0, p;\n\t}"
                     : "=r"(done) : "r"(mb), "r"(par) : "memory");
    }
}
__device__ __forceinline__ void ldsm4(uint32_t* r, uint32_t addr) {
    asm volatile("ldmatrix.sync.aligned.m8n8.x4.shared.b16 {%0,%1,%2,%3}, [%4];"
                 : "=r"(r[0]), "=r"(r[1]), "=r"(r[2]), "=r"(r[3]) : "r"(addr));
}
__device__ __forceinline__ void ldsm4t(uint32_t* r, uint32_t addr) {
    asm volatile("ldmatrix.sync.aligned.m8n8.x4.trans.shared.b16 {%0,%1,%2,%3}, [%4];"
                 : "=r"(r[0]), "=r"(r[1]), "=r"(r[2]), "=r"(r[3]) : "r"(addr));
}
__device__ __forceinline__ void mma16816(float* c, const uint32_t* a,
                                         uint32_t b0, uint32_t b1) {
    asm volatile("mma.sync.aligned.m16n8k16.row.col.f32.f16.f16.f32 "
                 "{%0,%1,%2,%3},{%4,%5,%6,%7},{%8,%9},{%0,%1,%2,%3};"
                 : "+f"(c[0]), "+f"(c[1]), "+f"(c[2]), "+f"(c[3])
                 : "r"(a[0]), "r"(a[1]), "r"(a[2]), "r"(a[3]), "r"(b0), "r"(b1));
}
__device__ __forceinline__ uint32_t h2bits(__half2 h) {
    return *reinterpret_cast<uint32_t*>(&h);
}
__device__ __forceinline__ void cvt_sts(float4 v, char* hi, char* lo, uint32_t off) {
    __half2 h01 = __floats2half2_rn(v.x, v.y);
    __half2 h23 = __floats2half2_rn(v.z, v.w);
    float2 f01 = __half22float2(h01);
    float2 f23 = __half22float2(h23);
    __half2 l01 = __floats2half2_rn(v.x - f01.x, v.y - f01.y);
    __half2 l23 = __floats2half2_rn(v.z - f23.x, v.w - f23.y);
    *(uint2*)(hi + off) = make_uint2(h2bits(h01), h2bits(h23));
    *(uint2*)(lo + off) = make_uint2(h2bits(l01), h2bits(l23));
}

// ---------------- precompute: K -> hi/lo fp16, V -> fp16 ----------------
__global__ void __launch_bounds__(256)
cvt_kernel(const float* __restrict__ K, const float* __restrict__ V)
{
    int idx = blockIdx.x * 256 + threadIdx.x;
    int tsel = idx >> 18;
    int rem  = idx & 262143;
    int d    = rem >> 11;
    int c4   = (rem & 2047) << 2;
    const float* src = tsel ? V : K;
    float4 v = *(const float4*)(src + (size_t)d * N_ + c4);
    __half2 h01 = __floats2half2_rn(v.x, v.y);
    __half2 h23 = __floats2half2_rn(v.z, v.w);
    __half* hi = tsel ? g_Vhi[d] : g_Khi[d];
    *(uint2*)(hi + c4) = make_uint2(h2bits(h01), h2bits(h23));
    if (!tsel) {
        float2 f01 = __half22float2(h01);
        float2 f23 = __half22float2(h23);
        __half2 l01 = __floats2half2_rn(v.x - f01.x, v.y - f01.y);
        __half2 l23 = __floats2half2_rn(v.z - f23.x, v.w - f23.y);
        *(uint2*)(g_Klo[d] + c4) = make_uint2(h2bits(l01), h2bits(l23));
    }
}

__global__ void __launch_bounds__(NTHREADS, 1)
attn_mma(const float* __restrict__ Q, float* __restrict__ O)
{
    extern __shared__ __align__(1024) char smem[];
    const uint32_t sb = smem_u32(smem);
    const int tid  = threadIdx.x;
    const int lane = tid & 31;
    const int w    = tid >> 5;
    const int qb    = blockIdx.x;
    const int qBase = qb * BQ;
    const int kBase = blockIdx.y * KVLEN;
    const int sp    = blockIdx.y;

    const uint32_t mb_full[3] = { sb + SMBAR, sb + SMBAR + 8, sb + SMBAR + 16 };
    const uint32_t mb_free[3] = { sb + SMBAR + 24, sb + SMBAR + 32, sb + SMBAR + 40 };
    const uint32_t mb_stag = sb + SMBAR + 48;

    if (tid == 0) {
        #pragma unroll
        for (int i = 0; i < 3; ++i) {
            mbar_init(mb_full[i], NTHREADS);
            mbar_init(mb_free[i], NTHREADS);
        }
        mbar_init(mb_stag, 128);
    }
    __syncthreads();

    // per-thread cp.async geometry
    int cpd[4], cpk[4];
    uint32_t cpo[4];
    #pragma unroll
    for (int it = 0; it < 4; ++it) {
        int f = tid + it * NTHREADS;           // 0..1023
        cpd[it] = f >> 3;
        cpk[it] = (f & 7) << 3;
        cpo[it] = (uint32_t)(cpd[it] * TSTR + cpk[it]) * 2;
    }

    auto issue_tile = [&](int k0, uint32_t dst) {
        #pragma unroll
        for (int it = 0; it < 4; ++it) {
            const int d = cpd[it], kg = k0 + cpk[it];
            cp16(dst + KH_OFF + cpo[it], g_Khi[d] + kg);
            cp16(dst + KL_OFF + cpo[it], g_Klo[d] + kg);
            cp16(dst + VH_OFF + cpo[it], g_Vhi[d] + kg);
        }
    };

    // ---- stage Q: hi -> SBUF (temp), lo -> SQLO; both log2e-scaled ----
    #pragma unroll
    for (int it = 0; it < 16; ++it) {
        int f = tid + it * NTHREADS;       // 4096 float4s
        int d = f >> 5;
        int qc = (f & 31) << 2;
        float4 v = *(const float4*)(Q + (size_t)d * N_ + qBase + qc);
        v.x *= LOG2E; v.y *= LOG2E; v.z *= LOG2E; v.w *= LOG2E;
        cvt_sts(v, smem + SBUF, smem + SQLO, (uint32_t)(d * QSTR + qc) * 2);
    }
    __syncthreads();

    // per-lane ldmatrix offsets
    const int q0 = w * 16;
    const uint32_t qa_pat =
        (uint32_t)(((((lane >> 4) << 3) + (lane & 7)) * QSTR +
                    q0 + (((lane >> 3) & 1) << 3)) * 2);
    const uint32_t kb_off =
        (uint32_t)(((((lane >> 3) & 1) << 3) + (lane & 7)) * TSTR +
                   (((lane >> 4) << 3))) * 2;
    const uint32_t vb_off =
        (uint32_t)((((lane >> 4) << 3) + (lane & 7)) * TSTR +
                   ((((lane >> 3) & 1) << 3))) * 2;

    // ---- preload Qhi fragments into registers (8 d-steps x 4 regs) ----
    uint32_t qh[8][4];
    {
        const uint32_t qa_hi = sb + SBUF + qa_pat;
        #pragma unroll
        for (int s = 0; s < 8; ++s)
            ldsm4t(qh[s], qa_hi + s * (16 * QSTR * 2));
    }
    __syncthreads();   // staging reads complete before SBUF becomes KV buffers

    // ---- prologue: tiles 0,1 into buffers 0,1 ----
    issue_tile(kBase, sb + SBUF);
    cpasync_mbar_arrive(mb_full[0]);
    issue_tile(kBase + BK, sb + SBUF + BUFB);
    cpasync_mbar_arrive(mb_full[1]);

    const uint32_t qa_lo = sb + SQLO + qa_pat;

    float oacc[16][4];
    #pragma unroll
    for (int i = 0; i < 16; ++i)
        #pragma unroll
        for (int j = 0; j < 4; ++j) oacc[i][j] = 0.0f;
    float m0 = -1e30f, m1 = -1e30f, l0 = 0.0f, l1 = 0.0f;

    // ---- stagger: group B (warps 4-7) starts ~half a tile late ----
    if (w >= 4) mbar_wait(mb_stag, 0);

    for (int t = 0; t < NT; ++t) {
        const int p = t % 3;
        const uint32_t bufK = sb + SBUF + (uint32_t)p * BUFB;
        const uint32_t bufV = bufK + VH_OFF;

        // ---- consume tile t ----
        mbar_wait(mb_full[p], (t / 3) & 1);

        // ---- S = Q^T K: d-outer, Qhi from regs, Qlo ldsm ----
        float acc[8][4];
        #pragma unroll
        for (int i = 0; i < 8; ++i)
            #pragma unroll
            for (int j = 0; j < 4; ++j) acc[i][j] = 0.0f;

        #pragma unroll
        for (int s = 0; s < 8; ++s) {          // d-steps of 16
            uint32_t al[4];
            ldsm4t(al, qa_lo + s * (16 * QSTR * 2));
            #pragma unroll
            for (int c = 0; c < 2; ++c) {      // key chunks of 32
                uint32_t bh0[4], bl0[4], bh1[4], bl1[4];
                uint32_t ka = bufK + kb_off + s * (16 * TSTR * 2) + c * 64;
                ldsm4t(bh0, ka + KH_OFF);
                ldsm4t(bl0, ka + KL_OFF);
                ldsm4t(bh1, ka + KH_OFF + 32);
                ldsm4t(bl1, ka + KL_OFF + 32);
                float* a0 = acc[4 * c];
                float* a1 = acc[4 * c + 1];
                float* a2 = acc[4 * c + 2];
                float* a3 = acc[4 * c + 3];
                mma16816(a0, qh[s], bh0[0], bh0[1]);
                mma16816(a1, qh[s], bh0[2], bh0[3]);
                mma16816(a2, qh[s], bh1[0], bh1[1]);
                mma16816(a3, qh[s], bh1[2], bh1[3]);
                mma16816(a0, qh[s], bl0[0], bl0[1]);
                mma16816(a1, qh[s], bl0[2], bl0[3]);
                mma16816(a2, qh[s], bl1[0], bl1[1]);
                mma16816(a3, qh[s], bl1[2], bl1[3]);
                mma16816(a0, al, bh0[0], bh0[1]);
                mma16816(a1, al, bh0[2], bh0[3]);
                mma16816(a2, al, bh1[0], bh1[1]);
                mma16816(a3, al, bh1[2], bh1[3]);
            }
        }

        // release group B after group A's first S-phase (sets the skew)
        if (t == 0 && w < 4) mbar_arrive(mb_stag);

        // ---- produce tile t+2 ----
        if (t + 2 < NT) {
            const int pp = (t + 2) % 3;
            const int m  = (t + 2) / 3;
            if (m >= 1) mbar_wait(mb_free[pp], (m - 1) & 1);
            issue_tile(kBase + (t + 2) * BK, sb + SBUF + (uint32_t)pp * BUFB);
            cpasync_mbar_arrive(mb_full[pp]);
        }

        // ---- per-chunk: softmax + PV ----
        #pragma unroll
        for (int c = 0; c < 2; ++c) {
            float (*ca)[4] = &acc[4 * c];

            float tm0 = -1e30f, tm1 = -1e30f;
            #pragma unroll
            for (int nt = 0; nt < 4; ++nt) {
                tm0 = fmaxf(tm0, fmaxf(ca[nt][0], ca[nt][1]));
                tm1 = fmaxf(tm1, fmaxf(ca[nt][2], ca[nt][3]));
            }
            tm0 = fmaxf(tm0, __shfl_xor_sync(0xffffffffu, tm0, 1));
            tm0 = fmaxf(tm0, __shfl_xor_sync(0xffffffffu, tm0, 2));
            tm1 = fmaxf(tm1, __shfl_xor_sync(0xffffffffu, tm1, 1));
            tm1 = fmaxf(tm1, __shfl_xor_sync(0xffffffffu, tm1, 2));

            bool upd = (tm0 > m0 + THRESH) || (tm1 > m1 + THRESH);
            if (__ballot_sync(0xffffffffu, upd)) {
                float nm0 = fmaxf(m0, tm0), nm1 = fmaxf(m1, tm1);
                float a0 = exp2f(m0 - nm0), a1 = exp2f(m1 - nm1);
                m0 = nm0; m1 = nm1; l0 *= a0; l1 *= a1;
                #pragma unroll
                for (int nt = 0; nt < 16; ++nt) {
                    oacc[nt][0] *= a0; oacc[nt][1] *= a0;
                    oacc[nt][2] *= a1; oacc[nt][3] *= a1;
                }
            }

            #pragma unroll
            for (int sh = 0; sh < 2; ++sh) {
                const int s = 2 * c + sh;      // global k-step
                uint32_t ah[4];
                #pragma unroll
                for (int half = 0; half < 2; ++half) {
                    float* av = ca[2 * sh + half];
                    float p0 = exp2f(av[0] - m0);
                    float p1 = exp2f(av[1] - m0);
                    float p2 = exp2f(av[2] - m1);
                    float p3 = exp2f(av[3] - m1);
                    l0 += p0 + p1; l1 += p2 + p3;
                    ah[2 * half]     = h2bits(__floats2half2_rn(p0, p1));
                    ah[2 * half + 1] = h2bits(__floats2half2_rn(p2, p3));
                }
                #pragma unroll
                for (int np = 0; np < 8; ++np) {   // d-tile pairs (16 dims)
                    uint32_t bh[4];
                    uint32_t va = bufV + vb_off + np * (16 * TSTR * 2) + s * 32;
                    ldsm4(bh, va);
                    mma16816(oacc[2 * np],     ah, bh[0], bh[1]);
                    mma16816(oacc[2 * np + 1], ah, bh[2], bh[3]);
                }
            }
        }

        mbar_arrive(mb_free[p]);   // done reading buffer p
    }

    // ---- epilogue: write partials ----
    l0 += __shfl_xor_sync(0xffffffffu, l0, 1);
    l0 += __shfl_xor_sync(0xffffffffu, l0, 2);
    l1 += __shfl_xor_sync(0xffffffffu, l1, 1);
    l1 += __shfl_xor_sync(0xffffffffu, l1, 2);

    const int qr0 = qBase + q0 + (lane >> 2);
    const int qr1 = qr0 + 8;
    if ((lane & 3) == 0) {
        g_m[sp][qr0] = m0; g_m[sp][qr1] = m1;
        g_l[sp][qr0] = l0; g_l[sp][qr1] = l1;
    }
    #pragma unroll
    for (int nt = 0; nt < 16; ++nt) {
        int d = nt * 8 + ((lane & 3) << 1);
        g_Op[sp][d][qr0]     = oacc[nt][0];
        g_Op[sp][d + 1][qr0] = oacc[nt][1];
        g_Op[sp][d][qr1]     = oacc[nt][2];
        g_Op[sp][d + 1][qr1] = oacc[nt][3];
    }

    // ---- fused combine: last CTA of this q-block merges the two splits ----
    __threadfence();           // release: partials visible device-wide
    __syncthreads();           // all threads' stores issued before the arrive
    volatile uint32_t* s_old = (volatile uint32_t*)(smem + SMBAR + 56);
    if (tid == 0) *s_old = atomicAdd(&g_sync[qb], 1u);
    __syncthreads();
    if (*s_old == 1u) {        // we are last: partner's release happened-before
        if (tid == 0) g_sync[qb] = 0u;    // reset for next graph replay
        __threadfence();       // acquire side
        for (int i = tid; i < (D_ * BQ) / 4; i += NTHREADS) {
            int d  = i >> 5;                       // BQ/4 = 32 groups per row
            int q4 = qBase + ((i & 31) << 2);
            float4 o1 = *(const float4*)&g_Op[0][d][q4];
            float4 o2 = *(const float4*)&g_Op[1][d][q4];
            float r[4];
            const float* po1 = &o1.x;
            const float* po2 = &o2.x;
            #pragma unroll
            for (int c = 0; c < 4; ++c) {
                float ma = g_m[0][q4 + c], mb = g_m[1][q4 + c];
                float la = g_l[0][q4 + c], lb = g_l[1][q4 + c];
                float M  = fmaxf(ma, mb);
                float wa = exp2f(ma - M), wb = exp2f(mb - M);
                r[c] = (wa * po1[c] + wb * po2[c]) / (wa * la + wb * lb);
            }
            *(float4*)(O + (size_t)d * N_ + q4) = make_float4(r[0], r[1], r[2], r[3]);
        }
    }
}

} // namespace

extern "C" void kernel_launch(void* const* d_in, const int* in_sizes, int n_in,
                              void* d_out, int out_size) {
    const float* Q = (const float*)d_in[0];
    const float* K = (const float*)d_in[1];
    const float* V = (const float*)d_in[2];
    float* O = (float*)d_out;

    cudaFuncSetAttribute(attn_mma, cudaFuncAttributeMaxDynamicSharedMemorySize,
                         SMEM_BYTES);
    cvt_kernel<<<2048, 256>>>(K, V);
    dim3 grid(N_ / BQ, SPLIT);
    attn_mma<<<grid, NTHREADS, SMEM_BYTES>>>(Q, O);
}

// round 16
// speedup vs baseline: 1.0207x; 1.0207x over previous
#include <cuda_runtime.h>
#include <cuda_fp16.h>
#include <cstdint>
#include <cstddef>

// ===========================================================================
// Flash attention via mma.sync.m16n8k16 (fp16-split for fp32 accuracy).
// Q,K,V fp32 [D=128, N=8192] feature-major. out[d,q] fp32.
// R16: R14 core (best: 205.2us) with the two noop padding launches removed;
//      separate combine kernel retained (R15 showed fusion costs more than
//      the launch overhead it saves).
// grid = (64 q-blocks, 2 kv-splits); combine kernel merges partials.
// ===========================================================================

namespace {

constexpr int D_ = 128;
constexpr int N_ = 8192;
constexpr int BQ = 128;
constexpr int BK = 64;
constexpr int SPLIT = 2;
constexpr int KVLEN = N_ / SPLIT;   // 4096
constexpr int NT = KVLEN / BK;      // 64 tiles
constexpr int NTHREADS = 256;

constexpr int QSTR = 136;           // halves per Q row (272 B, conflict-free)
constexpr int TSTR = 72;            // halves per K/V tile row (144 B)

// smem byte offsets
constexpr int SMBAR = 0;            // 7 mbarriers x 8 B
constexpr int SQLO  = 128;
constexpr int SBUF  = SQLO + D_ * QSTR * 2;         // 128+34816 = 34944
constexpr int SUB   = D_ * TSTR * 2;                // 18432 per sub-tile
constexpr int KH_OFF = 0, KL_OFF = SUB, VH_OFF = 2 * SUB;
constexpr int BUFB = 3 * SUB;                       // 55296
constexpr int NBUF = 3;
constexpr int SMEM_BYTES = SBUF + NBUF * BUFB;      // 200,832

constexpr float LOG2E  = 1.4426950408889634f;
constexpr float THRESH = 11.5f;                     // ~8 nats, in log2 units

// pre-split K (hi/lo) and V (single fp16), written once by cvt_kernel
__device__ __half g_Khi[D_][N_];
__device__ __half g_Klo[D_][N_];
__device__ __half g_Vhi[D_][N_];

// kv-split combine scratch (m in log2 units)
__device__ float g_Op[SPLIT][D_][N_];
__device__ float g_m[SPLIT][N_];
__device__ float g_l[SPLIT][N_];

__device__ __forceinline__ uint32_t smem_u32(const void* p) {
    uint32_t a;
    asm("{ .reg .u64 t; cvta.to.shared.u64 t, %1; cvt.u32.u64 %0, t; }" : "=r"(a) : "l"(p));
    return a;
}
__device__ __forceinline__ void cp16(uint32_t s, const void* g) {
    asm volatile("cp.async.cg.shared.global [%0], [%1], 16;\n" :: "r"(s), "l"(g));
}
__device__ __forceinline__ void mbar_init(uint32_t mb, uint32_t cnt) {
    asm volatile("mbarrier.init.shared.b64 [%0], %1;" :: "r"(mb), "r"(cnt) : "memory");
}
__device__ __forceinline__ void mbar_arrive(uint32_t mb) {
    uint64_t s;
    asm volatile("mbarrier.arrive.shared.b64 %0, [%1];" : "=l"(s) : "r"(mb) : "memory");
}
__device__ __forceinline__ void cpasync_mbar_arrive(uint32_t mb) {
    asm volatile("cp.async.mbarrier.arrive.noinc.shared.b64 [%0];" :: "r"(mb) : "memory");
}
__device__ __forceinline__ void mbar_wait(uint32_t mb, uint32_t par) {
    uint32_t done = 0;
    while (!done) {
        asm volatile("{\n\t.reg .pred p;\n\t"
                     "mbarrier.test_wait.parity.shared.b64 p, [%1], %2;\n\t"
                     "selp.b32 %0, 1, 0, p;\n\t}"
                     : "=r"(done) : "r"(mb), "r"(par) : "memory");
    }
}
__device__ __forceinline__ void ldsm4(uint32_t* r, uint32_t addr) {
    asm volatile("ldmatrix.sync.aligned.m8n8.x4.shared.b16 {%0,%1,%2,%3}, [%4];"
                 : "=r"(r[0]), "=r"(r[1]), "=r"(r[2]), "=r"(r[3]) : "r"(addr));
}
__device__ __forceinline__ void ldsm4t(uint32_t* r, uint32_t addr) {
    asm volatile("ldmatrix.sync.aligned.m8n8.x4.trans.shared.b16 {%0,%1,%2,%3}, [%4];"
                 : "=r"(r[0]), "=r"(r[1]), "=r"(r[2]), "=r"(r[3]) : "r"(addr));
}
__device__ __forceinline__ void mma16816(float* c, const uint32_t* a,
                                         uint32_t b0, uint32_t b1) {
    asm volatile("mma.sync.aligned.m16n8k16.row.col.f32.f16.f16.f32 "
                 "{%0,%1,%2,%3},{%4,%5,%6,%7},{%8,%9},{%0,%1,%2,%3};"
                 : "+f"(c[0]), "+f"(c[1]), "+f"(c[2]), "+f"(c[3])
                 : "r"(a[0]), "r"(a[1]), "r"(a[2]), "r"(a[3]), "r"(b0), "r"(b1));
}
__device__ __forceinline__ uint32_t h2bits(__half2 h) {
    return *reinterpret_cast<uint32_t*>(&h);
}
__device__ __forceinline__ void cvt_sts(float4 v, char* hi, char* lo, uint32_t off) {
    __half2 h01 = __floats2half2_rn(v.x, v.y);
    __half2 h23 = __floats2half2_rn(v.z, v.w);
    float2 f01 = __half22float2(h01);
    float2 f23 = __half22float2(h23);
    __half2 l01 = __floats2half2_rn(v.x - f01.x, v.y - f01.y);
    __half2 l23 = __floats2half2_rn(v.z - f23.x, v.w - f23.y);
    *(uint2*)(hi + off) = make_uint2(h2bits(h01), h2bits(h23));
    *(uint2*)(lo + off) = make_uint2(h2bits(l01), h2bits(l23));
}

// ---------------- precompute: K -> hi/lo fp16, V -> fp16 ----------------
__global__ void __launch_bounds__(256)
cvt_kernel(const float* __restrict__ K, const float* __restrict__ V)
{
    int idx = blockIdx.x * 256 + threadIdx.x;
    int tsel = idx >> 18;
    int rem  = idx & 262143;
    int d    = rem >> 11;
    int c4   = (rem & 2047) << 2;
    const float* src = tsel ? V : K;
    float4 v = *(const float4*)(src + (size_t)d * N_ + c4);
    __half2 h01 = __floats2half2_rn(v.x, v.y);
    __half2 h23 = __floats2half2_rn(v.z, v.w);
    __half* hi = tsel ? g_Vhi[d] : g_Khi[d];
    *(uint2*)(hi + c4) = make_uint2(h2bits(h01), h2bits(h23));
    if (!tsel) {
        float2 f01 = __half22float2(h01);
        float2 f23 = __half22float2(h23);
        __half2 l01 = __floats2half2_rn(v.x - f01.x, v.y - f01.y);
        __half2 l23 = __floats2half2_rn(v.z - f23.x, v.w - f23.y);
        *(uint2*)(g_Klo[d] + c4) = make_uint2(h2bits(l01), h2bits(l23));
    }
}

__global__ void __launch_bounds__(NTHREADS, 1)
attn_mma(const float* __restrict__ Q)
{
    extern __shared__ __align__(1024) char smem[];
    const uint32_t sb = smem_u32(smem);
    const int tid  = threadIdx.x;
    const int lane = tid & 31;
    const int w    = tid >> 5;
    const int qBase = blockIdx.x * BQ;
    const int kBase = blockIdx.y * KVLEN;
    const int sp    = blockIdx.y;

    const uint32_t mb_full[3] = { sb + SMBAR, sb + SMBAR + 8, sb + SMBAR + 16 };
    const uint32_t mb_free[3] = { sb + SMBAR + 24, sb + SMBAR + 32, sb + SMBAR + 40 };
    const uint32_t mb_stag = sb + SMBAR + 48;

    if (tid == 0) {
        #pragma unroll
        for (int i = 0; i < 3; ++i) {
            mbar_init(mb_full[i], NTHREADS);
            mbar_init(mb_free[i], NTHREADS);
        }
        mbar_init(mb_stag, 128);
    }
    __syncthreads();

    // per-thread cp.async geometry
    int cpd[4], cpk[4];
    uint32_t cpo[4];
    #pragma unroll
    for (int it = 0; it < 4; ++it) {
        int f = tid + it * NTHREADS;           // 0..1023
        cpd[it] = f >> 3;
        cpk[it] = (f & 7) << 3;
        cpo[it] = (uint32_t)(cpd[it] * TSTR + cpk[it]) * 2;
    }

    auto issue_tile = [&](int k0, uint32_t dst) {
        #pragma unroll
        for (int it = 0; it < 4; ++it) {
            const int d = cpd[it], kg = k0 + cpk[it];
            cp16(dst + KH_OFF + cpo[it], g_Khi[d] + kg);
            cp16(dst + KL_OFF + cpo[it], g_Klo[d] + kg);
            cp16(dst + VH_OFF + cpo[it], g_Vhi[d] + kg);
        }
    };

    // ---- stage Q: hi -> SBUF (temp), lo -> SQLO; both log2e-scaled ----
    #pragma unroll
    for (int it = 0; it < 16; ++it) {
        int f = tid + it * NTHREADS;       // 4096 float4s
        int d = f >> 5;
        int qc = (f & 31) << 2;
        float4 v = *(const float4*)(Q + (size_t)d * N_ + qBase + qc);
        v.x *= LOG2E; v.y *= LOG2E; v.z *= LOG2E; v.w *= LOG2E;
        cvt_sts(v, smem + SBUF, smem + SQLO, (uint32_t)(d * QSTR + qc) * 2);
    }
    __syncthreads();

    // per-lane ldmatrix offsets
    const int q0 = w * 16;
    const uint32_t qa_pat =
        (uint32_t)(((((lane >> 4) << 3) + (lane & 7)) * QSTR +
                    q0 + (((lane >> 3) & 1) << 3)) * 2);
    const uint32_t kb_off =
        (uint32_t)(((((lane >> 3) & 1) << 3) + (lane & 7)) * TSTR +
                   (((lane >> 4) << 3))) * 2;
    const uint32_t vb_off =
        (uint32_t)((((lane >> 4) << 3) + (lane & 7)) * TSTR +
                   ((((lane >> 3) & 1) << 3))) * 2;

    // ---- preload Qhi fragments into registers (8 d-steps x 4 regs) ----
    uint32_t qh[8][4];
    {
        const uint32_t qa_hi = sb + SBUF + qa_pat;
        #pragma unroll
        for (int s = 0; s < 8; ++s)
            ldsm4t(qh[s], qa_hi + s * (16 * QSTR * 2));
    }
    __syncthreads();   // staging reads complete before SBUF becomes KV buffers

    // ---- prologue: tiles 0,1 into buffers 0,1 ----
    issue_tile(kBase, sb + SBUF);
    cpasync_mbar_arrive(mb_full[0]);
    issue_tile(kBase + BK, sb + SBUF + BUFB);
    cpasync_mbar_arrive(mb_full[1]);

    const uint32_t qa_lo = sb + SQLO + qa_pat;

    float oacc[16][4];
    #pragma unroll
    for (int i = 0; i < 16; ++i)
        #pragma unroll
        for (int j = 0; j < 4; ++j) oacc[i][j] = 0.0f;
    float m0 = -1e30f, m1 = -1e30f, l0 = 0.0f, l1 = 0.0f;

    // ---- stagger: group B (warps 4-7) starts ~half a tile late ----
    if (w >= 4) mbar_wait(mb_stag, 0);

    for (int t = 0; t < NT; ++t) {
        const int p = t % 3;
        const uint32_t bufK = sb + SBUF + (uint32_t)p * BUFB;
        const uint32_t bufV = bufK + VH_OFF;

        // ---- consume tile t ----
        mbar_wait(mb_full[p], (t / 3) & 1);

        // ---- S = Q^T K: d-outer, Qhi from regs, Qlo ldsm ----
        float acc[8][4];
        #pragma unroll
        for (int i = 0; i < 8; ++i)
            #pragma unroll
            for (int j = 0; j < 4; ++j) acc[i][j] = 0.0f;

        #pragma unroll
        for (int s = 0; s < 8; ++s) {          // d-steps of 16
            uint32_t al[4];
            ldsm4t(al, qa_lo + s * (16 * QSTR * 2));
            #pragma unroll
            for (int c = 0; c < 2; ++c) {      // key chunks of 32
                uint32_t bh0[4], bl0[4], bh1[4], bl1[4];
                uint32_t ka = bufK + kb_off + s * (16 * TSTR * 2) + c * 64;
                ldsm4t(bh0, ka + KH_OFF);
                ldsm4t(bl0, ka + KL_OFF);
                ldsm4t(bh1, ka + KH_OFF + 32);
                ldsm4t(bl1, ka + KL_OFF + 32);
                float* a0 = acc[4 * c];
                float* a1 = acc[4 * c + 1];
                float* a2 = acc[4 * c + 2];
                float* a3 = acc[4 * c + 3];
                mma16816(a0, qh[s], bh0[0], bh0[1]);
                mma16816(a1, qh[s], bh0[2], bh0[3]);
                mma16816(a2, qh[s], bh1[0], bh1[1]);
                mma16816(a3, qh[s], bh1[2], bh1[3]);
                mma16816(a0, qh[s], bl0[0], bl0[1]);
                mma16816(a1, qh[s], bl0[2], bl0[3]);
                mma16816(a2, qh[s], bl1[0], bl1[1]);
                mma16816(a3, qh[s], bl1[2], bl1[3]);
                mma16816(a0, al, bh0[0], bh0[1]);
                mma16816(a1, al, bh0[2], bh0[3]);
                mma16816(a2, al, bh1[0], bh1[1]);
                mma16816(a3, al, bh1[2], bh1[3]);
            }
        }

        // release group B after group A's first S-phase (sets the skew)
        if (t == 0 && w < 4) mbar_arrive(mb_stag);

        // ---- produce tile t+2 ----
        if (t + 2 < NT) {
            const int pp = (t + 2) % 3;
            const int m  = (t + 2) / 3;
            if (m >= 1) mbar_wait(mb_free[pp], (m - 1) & 1);
            issue_tile(kBase + (t + 2) * BK, sb + SBUF + (uint32_t)pp * BUFB);
            cpasync_mbar_arrive(mb_full[pp]);
        }

        // ---- per-chunk: softmax + PV ----
        #pragma unroll
        for (int c = 0; c < 2; ++c) {
            float (*ca)[4] = &acc[4 * c];

            float tm0 = -1e30f, tm1 = -1e30f;
            #pragma unroll
            for (int nt = 0; nt < 4; ++nt) {
                tm0 = fmaxf(tm0, fmaxf(ca[nt][0], ca[nt][1]));
                tm1 = fmaxf(tm1, fmaxf(ca[nt][2], ca[nt][3]));
            }
            tm0 = fmaxf(tm0, __shfl_xor_sync(0xffffffffu, tm0, 1));
            tm0 = fmaxf(tm0, __shfl_xor_sync(0xffffffffu, tm0, 2));
            tm1 = fmaxf(tm1, __shfl_xor_sync(0xffffffffu, tm1, 1));
            tm1 = fmaxf(tm1, __shfl_xor_sync(0xffffffffu, tm1, 2));

            bool upd = (tm0 > m0 + THRESH) || (tm1 > m1 + THRESH);
            if (__ballot_sync(0xffffffffu, upd)) {
                float nm0 = fmaxf(m0, tm0), nm1 = fmaxf(m1, tm1);
                float a0 = exp2f(m0 - nm0), a1 = exp2f(m1 - nm1);
                m0 = nm0; m1 = nm1; l0 *= a0; l1 *= a1;
                #pragma unroll
                for (int nt = 0; nt < 16; ++nt) {
                    oacc[nt][0] *= a0; oacc[nt][1] *= a0;
                    oacc[nt][2] *= a1; oacc[nt][3] *= a1;
                }
            }

            #pragma unroll
            for (int sh = 0; sh < 2; ++sh) {
                const int s = 2 * c + sh;      // global k-step
                uint32_t ah[4];
                #pragma unroll
                for (int half = 0; half < 2; ++half) {
                    float* av = ca[2 * sh + half];
                    float p0 = exp2f(av[0] - m0);
                    float p1 = exp2f(av[1] - m0);
                    float p2 = exp2f(av[2] - m1);
                    float p3 = exp2f(av[3] - m1);
                    l0 += p0 + p1; l1 += p2 + p3;
                    ah[2 * half]     = h2bits(__floats2half2_rn(p0, p1));
                    ah[2 * half + 1] = h2bits(__floats2half2_rn(p2, p3));
                }
                #pragma unroll
                for (int np = 0; np < 8; ++np) {   // d-tile pairs (16 dims)
                    uint32_t bh[4];
                    uint32_t va = bufV + vb_off + np * (16 * TSTR * 2) + s * 32;
                    ldsm4(bh, va);
                    mma16816(oacc[2 * np],     ah, bh[0], bh[1]);
                    mma16816(oacc[2 * np + 1], ah, bh[2], bh[3]);
                }
            }
        }

        mbar_arrive(mb_free[p]);   // done reading buffer p
    }

    // ---- epilogue ----
    l0 += __shfl_xor_sync(0xffffffffu, l0, 1);
    l0 += __shfl_xor_sync(0xffffffffu, l0, 2);
    l1 += __shfl_xor_sync(0xffffffffu, l1, 1);
    l1 += __shfl_xor_sync(0xffffffffu, l1, 2);

    const int qr0 = qBase + q0 + (lane >> 2);
    const int qr1 = qr0 + 8;
    if ((lane & 3) == 0) {
        g_m[sp][qr0] = m0; g_m[sp][qr1] = m1;
        g_l[sp][qr0] = l0; g_l[sp][qr1] = l1;
    }
    #pragma unroll
    for (int nt = 0; nt < 16; ++nt) {
        int d = nt * 8 + ((lane & 3) << 1);
        g_Op[sp][d][qr0]     = oacc[nt][0];
        g_Op[sp][d + 1][qr0] = oacc[nt][1];
        g_Op[sp][d][qr1]     = oacc[nt][2];
        g_Op[sp][d + 1][qr1] = oacc[nt][3];
    }
}

__global__ void __launch_bounds__(256)
combine_kernel(float* __restrict__ O)
{
    int idx = blockIdx.x * 256 + threadIdx.x;    // 262144 float4s
    int d  = idx >> 11;
    int q4 = (idx & 2047) << 2;
    float4 o1 = *(const float4*)&g_Op[0][d][q4];
    float4 o2 = *(const float4*)&g_Op[1][d][q4];
    float r[4];
    const float* po1 = &o1.x;
    const float* po2 = &o2.x;
    #pragma unroll
    for (int c = 0; c < 4; ++c) {
        float m1 = g_m[0][q4 + c], m2 = g_m[1][q4 + c];
        float l1 = g_l[0][q4 + c], l2 = g_l[1][q4 + c];
        float M  = fmaxf(m1, m2);
        float w1 = exp2f(m1 - M), w2 = exp2f(m2 - M);
        r[c] = (w1 * po1[c] + w2 * po2[c]) / (w1 * l1 + w2 * l2);
    }
    *(float4*)(O + (size_t)d * N_ + q4) = make_float4(r[0], r[1], r[2], r[3]);
}

} // namespace

extern "C" void kernel_launch(void* const* d_in, const int* in_sizes, int n_in,
                              void* d_out, int out_size) {
    const float* Q = (const float*)d_in[0];
    const float* K = (const float*)d_in[1];
    const float* V = (const float*)d_in[2];
    float* O = (float*)d_out;

    cudaFuncSetAttribute(attn_mma, cudaFuncAttributeMaxDynamicSharedMemorySize,
                         SMEM_BYTES);
    cvt_kernel<<<2048, 256>>>(K, V);
    dim3 grid(N_ / BQ, SPLIT);
    attn_mma<<<grid, NTHREADS, SMEM_BYTES>>>(Q);
    combine_kernel<<<(D_ * N_ / 4) / 256, 256>>>(O);
}

// round 17
// speedup vs baseline: 1.1177x; 1.0951x over previous
#include <cuda_runtime.h>
#include <cuda_fp16.h>
#include <cstdint>
#include <cstddef>

// ===========================================================================
// Flash attention via mma.sync.m16n8k16 (fp16-split for fp32 accuracy).
// Q,K,V fp32 [D=128, N=8192] feature-major. out[d,q] fp32.
// R17: R14 core, balanced flat decomposition — 8192 (qb,kv) tiles cut into
//      147 chunks of <=56 tiles (one CTA each; <=2 q-block pieces per CTA;
//      <=4 partial slots per q-block). Makespan 64 -> 56 tiles, all SMs busy.
// ===========================================================================

namespace {

constexpr int D_ = 128;
constexpr int N_ = 8192;
constexpr int BQ = 128;
constexpr int BK = 64;
constexpr int TOT_TILES = (N_ / BQ) * (N_ / BK);   // 64 qb x 128 kv = 8192
constexpr int CHUNK = 56;
constexpr int NCHUNK = (TOT_TILES + CHUNK - 1) / CHUNK;   // 147
constexpr int NSLOT = 4;
constexpr int NTHREADS = 256;

constexpr int QSTR = 136;           // halves per Q row (272 B, conflict-free)
constexpr int TSTR = 72;            // halves per K/V tile row (144 B)

// smem byte offsets
constexpr int SMBAR = 0;            // 7 mbarriers x 8 B
constexpr int SQLO  = 128;
constexpr int SBUF  = SQLO + D_ * QSTR * 2;         // 128+34816 = 34944
constexpr int SUB   = D_ * TSTR * 2;                // 18432 per sub-tile
constexpr int KH_OFF = 0, KL_OFF = SUB, VH_OFF = 2 * SUB;
constexpr int BUFB = 3 * SUB;                       // 55296
constexpr int NBUF = 3;
constexpr int SMEM_BYTES = SBUF + NBUF * BUFB;      // 200,832

constexpr float LOG2E  = 1.4426950408889634f;
constexpr float THRESH = 11.5f;                     // ~8 nats, in log2 units

// pre-split K (hi/lo) and V (single fp16), written once by cvt_kernel
__device__ __half g_Khi[D_][N_];
__device__ __half g_Klo[D_][N_];
__device__ __half g_Vhi[D_][N_];

// combine scratch (m in log2 units); g_m re-initialized to -1e30 each run
__device__ float g_Op[NSLOT][D_][N_];
__device__ float g_m[NSLOT][N_];
__device__ float g_l[NSLOT][N_];

__device__ __forceinline__ uint32_t smem_u32(const void* p) {
    uint32_t a;
    asm("{ .reg .u64 t; cvta.to.shared.u64 t, %1; cvt.u32.u64 %0, t; }" : "=r"(a) : "l"(p));
    return a;
}
__device__ __forceinline__ void cp16(uint32_t s, const void* g) {
    asm volatile("cp.async.cg.shared.global [%0], [%1], 16;\n" :: "r"(s), "l"(g));
}
__device__ __forceinline__ void mbar_init(uint32_t mb, uint32_t cnt) {
    asm volatile("mbarrier.init.shared.b64 [%0], %1;" :: "r"(mb), "r"(cnt) : "memory");
}
__device__ __forceinline__ void mbar_arrive(uint32_t mb) {
    uint64_t s;
    asm volatile("mbarrier.arrive.shared.b64 %0, [%1];" : "=l"(s) : "r"(mb) : "memory");
}
__device__ __forceinline__ void cpasync_mbar_arrive(uint32_t mb) {
    asm volatile("cp.async.mbarrier.arrive.noinc.shared.b64 [%0];" :: "r"(mb) : "memory");
}
__device__ __forceinline__ void mbar_wait(uint32_t mb, uint32_t par) {
    uint32_t done = 0;
    while (!done) {
        asm volatile("{\n\t.reg .pred p;\n\t"
                     "mbarrier.test_wait.parity.shared.b64 p, [%1], %2;\n\t"
                     "selp.b32 %0, 1, 0, p;\n\t}"
                     : "=r"(done) : "r"(mb), "r"(par) : "memory");
    }
}
__device__ __forceinline__ void ldsm4(uint32_t* r, uint32_t addr) {
    asm volatile("ldmatrix.sync.aligned.m8n8.x4.shared.b16 {%0,%1,%2,%3}, [%4];"
                 : "=r"(r[0]), "=r"(r[1]), "=r"(r[2]), "=r"(r[3]) : "r"(addr));
}
__device__ __forceinline__ void ldsm4t(uint32_t* r, uint32_t addr) {
    asm volatile("ldmatrix.sync.aligned.m8n8.x4.trans.shared.b16 {%0,%1,%2,%3}, [%4];"
                 : "=r"(r[0]), "=r"(r[1]), "=r"(r[2]), "=r"(r[3]) : "r"(addr));
}
__device__ __forceinline__ void mma16816(float* c, const uint32_t* a,
                                         uint32_t b0, uint32_t b1) {
    asm volatile("mma.sync.aligned.m16n8k16.row.col.f32.f16.f16.f32 "
                 "{%0,%1,%2,%3},{%4,%5,%6,%7},{%8,%9},{%0,%1,%2,%3};"
                 : "+f"(c[0]), "+f"(c[1]), "+f"(c[2]), "+f"(c[3])
                 : "r"(a[0]), "r"(a[1]), "r"(a[2]), "r"(a[3]), "r"(b0), "r"(b1));
}
__device__ __forceinline__ uint32_t h2bits(__half2 h) {
    return *reinterpret_cast<uint32_t*>(&h);
}
__device__ __forceinline__ void cvt_sts(float4 v, char* hi, char* lo, uint32_t off) {
    __half2 h01 = __floats2half2_rn(v.x, v.y);
    __half2 h23 = __floats2half2_rn(v.z, v.w);
    float2 f01 = __half22float2(h01);
    float2 f23 = __half22float2(h23);
    __half2 l01 = __floats2half2_rn(v.x - f01.x, v.y - f01.y);
    __half2 l23 = __floats2half2_rn(v.z - f23.x, v.w - f23.y);
    *(uint2*)(hi + off) = make_uint2(h2bits(h01), h2bits(h23));
    *(uint2*)(lo + off) = make_uint2(h2bits(l01), h2bits(l23));
}

// ---------------- precompute: K -> hi/lo fp16, V -> fp16; init g_m ----------
__global__ void __launch_bounds__(256)
cvt_kernel(const float* __restrict__ K, const float* __restrict__ V)
{
    int idx = blockIdx.x * 256 + threadIdx.x;
    if (idx < NSLOT * N_) ((float*)g_m)[idx] = -1e30f;   // neutralize stale slots
    int tsel = idx >> 18;
    int rem  = idx & 262143;
    int d    = rem >> 11;
    int c4   = (rem & 2047) << 2;
    const float* src = tsel ? V : K;
    float4 v = *(const float4*)(src + (size_t)d * N_ + c4);
    __half2 h01 = __floats2half2_rn(v.x, v.y);
    __half2 h23 = __floats2half2_rn(v.z, v.w);
    __half* hi = tsel ? g_Vhi[d] : g_Khi[d];
    *(uint2*)(hi + c4) = make_uint2(h2bits(h01), h2bits(h23));
    if (!tsel) {
        float2 f01 = __half22float2(h01);
        float2 f23 = __half22float2(h23);
        __half2 l01 = __floats2half2_rn(v.x - f01.x, v.y - f01.y);
        __half2 l23 = __floats2half2_rn(v.z - f23.x, v.w - f23.y);
        *(uint2*)(g_Klo[d] + c4) = make_uint2(h2bits(l01), h2bits(l23));
    }
}

__global__ void __launch_bounds__(NTHREADS, 1)
attn_mma(const float* __restrict__ Q)
{
    extern __shared__ __align__(1024) char smem[];
    const uint32_t sb = smem_u32(smem);
    const int tid  = threadIdx.x;
    const int lane = tid & 31;
    const int w    = tid >> 5;
    const int chunk = blockIdx.x;
    const int t_begin = chunk * CHUNK;
    const int t_end   = min(TOT_TILES, t_begin + CHUNK);

    const uint32_t mb_full[3] = { sb + SMBAR, sb + SMBAR + 8, sb + SMBAR + 16 };
    const uint32_t mb_free[3] = { sb + SMBAR + 24, sb + SMBAR + 32, sb + SMBAR + 40 };
    const uint32_t mb_stag = sb + SMBAR + 48;

    if (tid == 0) {
        #pragma unroll
        for (int i = 0; i < 3; ++i) {
            mbar_init(mb_full[i], NTHREADS);
            mbar_init(mb_free[i], NTHREADS);
        }
        mbar_init(mb_stag, 128);
    }
    __syncthreads();

    // per-thread cp.async geometry
    int cpd[4], cpk[4];
    uint32_t cpo[4];
    #pragma unroll
    for (int it = 0; it < 4; ++it) {
        int f = tid + it * NTHREADS;           // 0..1023
        cpd[it] = f >> 3;
        cpk[it] = (f & 7) << 3;
        cpo[it] = (uint32_t)(cpd[it] * TSTR + cpk[it]) * 2;
    }

    auto issue_tile = [&](int k0, uint32_t dst) {
        #pragma unroll
        for (int it = 0; it < 4; ++it) {
            const int d = cpd[it], kg = k0 + cpk[it];
            cp16(dst + KH_OFF + cpo[it], g_Khi[d] + kg);
            cp16(dst + KL_OFF + cpo[it], g_Klo[d] + kg);
            cp16(dst + VH_OFF + cpo[it], g_Vhi[d] + kg);
        }
    };

    // per-lane ldmatrix offsets
    const int q0 = w * 16;
    const uint32_t qa_pat =
        (uint32_t)(((((lane >> 4) << 3) + (lane & 7)) * QSTR +
                    q0 + (((lane >> 3) & 1) << 3)) * 2);
    const uint32_t kb_off =
        (uint32_t)(((((lane >> 3) & 1) << 3) + (lane & 7)) * TSTR +
                   (((lane >> 4) << 3))) * 2;
    const uint32_t vb_off =
        (uint32_t)((((lane >> 4) << 3) + (lane & 7)) * TSTR +
                   ((((lane >> 3) & 1) << 3))) * 2;
    const uint32_t qa_lo = sb + SQLO + qa_pat;

    int ringpos = 0;       // cumulative produced/consumed tile count (ring phase)
    int piece_par = 0;     // stagger barrier parity
    int t = t_begin;

    while (t < t_end) {
        const int qb    = t >> 7;
        const int qBase = qb * BQ;
        const int nt    = min(t_end, (qb + 1) << 7) - t;
        const int kv0   = (t & 127) * BK;          // kv element offset of tile 0

        // ---- ring quiesced (all prior consumes done) before reusing SBUF ----
        __syncthreads();

        // ---- stage Q for this q-block: hi -> SBUF scratch, lo -> SQLO ----
        #pragma unroll
        for (int it = 0; it < 16; ++it) {
            int f = tid + it * NTHREADS;       // 4096 float4s
            int d = f >> 5;
            int qc = (f & 31) << 2;
            float4 v = *(const float4*)(Q + (size_t)d * N_ + qBase + qc);
            v.x *= LOG2E; v.y *= LOG2E; v.z *= LOG2E; v.w *= LOG2E;
            cvt_sts(v, smem + SBUF, smem + SQLO, (uint32_t)(d * QSTR + qc) * 2);
        }
        __syncthreads();

        uint32_t qh[8][4];
        {
            const uint32_t qa_hi = sb + SBUF + qa_pat;
            #pragma unroll
            for (int s = 0; s < 8; ++s)
                ldsm4t(qh[s], qa_hi + s * (16 * QSTR * 2));
        }
        __syncthreads();   // staging reads done before slot0 refilled by cp.async

        // ---- prologue: produce local tiles 0..min(2,nt)-1 ----
        for (int j = 0; j < min(2, nt); ++j) {
            const int pos = ringpos + j;
            const int s = pos % 3;
            if (pos >= 3) mbar_wait(mb_free[s], (pos / 3 - 1) & 1);
            issue_tile(kv0 + j * BK, sb + SBUF + (uint32_t)s * BUFB);
            cpasync_mbar_arrive(mb_full[s]);
        }

        float oacc[16][4];
        #pragma unroll
        for (int i = 0; i < 16; ++i)
            #pragma unroll
            for (int j = 0; j < 4; ++j) oacc[i][j] = 0.0f;
        float m0 = -1e30f, m1 = -1e30f, l0 = 0.0f, l1 = 0.0f;

        // ---- stagger: warps 4-7 start ~half a tile late each piece ----
        if (w >= 4) mbar_wait(mb_stag, piece_par);

        for (int tt = 0; tt < nt; ++tt) {
            const int pos = ringpos + tt;
            const int p = pos % 3;
            const uint32_t bufK = sb + SBUF + (uint32_t)p * BUFB;
            const uint32_t bufV = bufK + VH_OFF;

            mbar_wait(mb_full[p], (pos / 3) & 1);

            // ---- S = Q^T K: d-outer, Qhi regs, Qlo ldsm ----
            float acc[8][4];
            #pragma unroll
            for (int i = 0; i < 8; ++i)
                #pragma unroll
                for (int j = 0; j < 4; ++j) acc[i][j] = 0.0f;

            #pragma unroll
            for (int s = 0; s < 8; ++s) {
                uint32_t al[4];
                ldsm4t(al, qa_lo + s * (16 * QSTR * 2));
                #pragma unroll
                for (int c = 0; c < 2; ++c) {
                    uint32_t bh0[4], bl0[4], bh1[4], bl1[4];
                    uint32_t ka = bufK + kb_off + s * (16 * TSTR * 2) + c * 64;
                    ldsm4t(bh0, ka + KH_OFF);
                    ldsm4t(bl0, ka + KL_OFF);
                    ldsm4t(bh1, ka + KH_OFF + 32);
                    ldsm4t(bl1, ka + KL_OFF + 32);
                    float* a0 = acc[4 * c];
                    float* a1 = acc[4 * c + 1];
                    float* a2 = acc[4 * c + 2];
                    float* a3 = acc[4 * c + 3];
                    mma16816(a0, qh[s], bh0[0], bh0[1]);
                    mma16816(a1, qh[s], bh0[2], bh0[3]);
                    mma16816(a2, qh[s], bh1[0], bh1[1]);
                    mma16816(a3, qh[s], bh1[2], bh1[3]);
                    mma16816(a0, qh[s], bl0[0], bl0[1]);
                    mma16816(a1, qh[s], bl0[2], bl0[3]);
                    mma16816(a2, qh[s], bl1[0], bl1[1]);
                    mma16816(a3, qh[s], bl1[2], bl1[3]);
                    mma16816(a0, al, bh0[0], bh0[1]);
                    mma16816(a1, al, bh0[2], bh0[3]);
                    mma16816(a2, al, bh1[0], bh1[1]);
                    mma16816(a3, al, bh1[2], bh1[3]);
                }
            }

            if (tt == 0 && w < 4) mbar_arrive(mb_stag);

            // ---- produce local tile tt+2 ----
            if (tt + 2 < nt) {
                const int pp = ringpos + tt + 2;
                const int s2 = pp % 3;
                if (pp >= 3) mbar_wait(mb_free[s2], (pp / 3 - 1) & 1);
                issue_tile(kv0 + (tt + 2) * BK, sb + SBUF + (uint32_t)s2 * BUFB);
                cpasync_mbar_arrive(mb_full[s2]);
            }

            // ---- per-chunk: softmax + PV ----
            #pragma unroll
            for (int c = 0; c < 2; ++c) {
                float (*ca)[4] = &acc[4 * c];

                float tm0 = -1e30f, tm1 = -1e30f;
                #pragma unroll
                for (int nt2 = 0; nt2 < 4; ++nt2) {
                    tm0 = fmaxf(tm0, fmaxf(ca[nt2][0], ca[nt2][1]));
                    tm1 = fmaxf(tm1, fmaxf(ca[nt2][2], ca[nt2][3]));
                }
                tm0 = fmaxf(tm0, __shfl_xor_sync(0xffffffffu, tm0, 1));
                tm0 = fmaxf(tm0, __shfl_xor_sync(0xffffffffu, tm0, 2));
                tm1 = fmaxf(tm1, __shfl_xor_sync(0xffffffffu, tm1, 1));
                tm1 = fmaxf(tm1, __shfl_xor_sync(0xffffffffu, tm1, 2));

                bool upd = (tm0 > m0 + THRESH) || (tm1 > m1 + THRESH);
                if (__ballot_sync(0xffffffffu, upd)) {
                    float nm0 = fmaxf(m0, tm0), nm1 = fmaxf(m1, tm1);
                    float a0 = exp2f(m0 - nm0), a1 = exp2f(m1 - nm1);
                    m0 = nm0; m1 = nm1; l0 *= a0; l1 *= a1;
                    #pragma unroll
                    for (int nt2 = 0; nt2 < 16; ++nt2) {
                        oacc[nt2][0] *= a0; oacc[nt2][1] *= a0;
                        oacc[nt2][2] *= a1; oacc[nt2][3] *= a1;
                    }
                }

                #pragma unroll
                for (int sh = 0; sh < 2; ++sh) {
                    const int s = 2 * c + sh;
                    uint32_t ah[4];
                    #pragma unroll
                    for (int half = 0; half < 2; ++half) {
                        float* av = ca[2 * sh + half];
                        float p0 = exp2f(av[0] - m0);
                        float p1 = exp2f(av[1] - m0);
                        float p2 = exp2f(av[2] - m1);
                        float p3 = exp2f(av[3] - m1);
                        l0 += p0 + p1; l1 += p2 + p3;
                        ah[2 * half]     = h2bits(__floats2half2_rn(p0, p1));
                        ah[2 * half + 1] = h2bits(__floats2half2_rn(p2, p3));
                    }
                    #pragma unroll
                    for (int np = 0; np < 8; ++np) {
                        uint32_t bh[4];
                        uint32_t va = bufV + vb_off + np * (16 * TSTR * 2) + s * 32;
                        ldsm4(bh, va);
                        mma16816(oacc[2 * np],     ah, bh[0], bh[1]);
                        mma16816(oacc[2 * np + 1], ah, bh[2], bh[3]);
                    }
                }
            }

            mbar_arrive(mb_free[p]);
        }

        // ---- piece epilogue: write partials to this piece's slot ----
        float L0 = l0, L1 = l1;
        L0 += __shfl_xor_sync(0xffffffffu, L0, 1);
        L0 += __shfl_xor_sync(0xffffffffu, L0, 2);
        L1 += __shfl_xor_sync(0xffffffffu, L1, 1);
        L1 += __shfl_xor_sync(0xffffffffu, L1, 2);

        const int slot = chunk - ((qb << 7) / CHUNK);   // 0..3
        const int qr0 = qBase + q0 + (lane >> 2);
        const int qr1 = qr0 + 8;
        if ((lane & 3) == 0) {
            g_m[slot][qr0] = m0; g_m[slot][qr1] = m1;
            g_l[slot][qr0] = L0; g_l[slot][qr1] = L1;
        }
        #pragma unroll
        for (int nt2 = 0; nt2 < 16; ++nt2) {
            int d = nt2 * 8 + ((lane & 3) << 1);
            g_Op[slot][d][qr0]     = oacc[nt2][0];
            g_Op[slot][d + 1][qr0] = oacc[nt2][1];
            g_Op[slot][d][qr1]     = oacc[nt2][2];
            g_Op[slot][d + 1][qr1] = oacc[nt2][3];
        }

        ringpos += nt;
        piece_par ^= 1;
        t += nt;
    }
}

__global__ void __launch_bounds__(256)
combine_kernel(float* __restrict__ O)
{
    int idx = blockIdx.x * 256 + threadIdx.x;    // 262144 float4s
    int d  = idx >> 11;
    int q4 = (idx & 2047) << 2;
    float4 op[NSLOT];
    #pragma unroll
    for (int s = 0; s < NSLOT; ++s)
        op[s] = *(const float4*)&g_Op[s][d][q4];
    float r[4];
    #pragma unroll
    for (int c = 0; c < 4; ++c) {
        float M = -1e30f;
        #pragma unroll
        for (int s = 0; s < NSLOT; ++s) M = fmaxf(M, g_m[s][q4 + c]);
        float num = 0.0f, den = 0.0f;
        #pragma unroll
        for (int s = 0; s < NSLOT; ++s) {
            float wgt = exp2f(g_m[s][q4 + c] - M);
            num += wgt * (&op[s].x)[c];
            den += wgt * g_l[s][q4 + c];
        }
        r[c] = num / den;
    }
    *(float4*)(O + (size_t)d * N_ + q4) = make_float4(r[0], r[1], r[2], r[3]);
}

} // namespace

extern "C" void kernel_launch(void* const* d_in, const int* in_sizes, int n_in,
                              void* d_out, int out_size) {
    const float* Q = (const float*)d_in[0];
    const float* K = (const float*)d_in[1];
    const float* V = (const float*)d_in[2];
    float* O = (float*)d_out;

    cudaFuncSetAttribute(attn_mma, cudaFuncAttributeMaxDynamicSharedMemorySize,
                         SMEM_BYTES);
    cvt_kernel<<<2048, 256>>>(K, V);
    attn_mma<<<NCHUNK, NTHREADS, SMEM_BYTES>>>(Q);
    combine_kernel<<<(D_ * N_ / 4) / 256, 256>>>(O);
}